// round 13
// baseline (speedup 1.0000x reference)
#include <cuda_runtime.h>
#include <cstdint>

#define BS_  16
#define SEQQ 2048
#define DIM  1024
#define KDIM 1024
#define AH   64
#define HR   256
#define RANKD 16
#define KR   64
#define LQ   128
#define HID  2048

// ---- scratch (no allocations allowed; __device__ globals are the sanctioned path) ----
__device__ float g_Qp [BS_*SEQQ*DIM];
__device__ float g_Kp [BS_*KDIM*DIM];
__device__ float g_Vp [BS_*KDIM*DIM];
__device__ float g_kf [BS_*AH*HR*RANKD];
__device__ float g_vf [BS_*AH*HR*RANKD];
__device__ float g_ctx[BS_*SEQQ*DIM];
__device__ float g_h1 [BS_*SEQQ*HID];
__device__ float g_y  [BS_*SEQQ*DIM];

// ============================================================================
// TF32 tensor-core GEMM: C[m,n] = sum_k A[m,k]*B[n,k] + bias[n]
// A row-major [M,K], B row-major [N,K]. M%128==0, N%128==0, K%32==0.
// 128x128x32 CTA tile, 8 warps (4m x 2n), warp tile 32x64, m16n8k8 tf32 MMA.
// Smem stride 36 words -> conflict-free fragment reads.
// ============================================================================
__device__ __forceinline__ uint32_t f2tf(float x) {
    uint32_t r;
    asm("cvt.rna.tf32.f32 %0, %1;" : "=r"(r) : "f"(x));
    return r;
}

__device__ __forceinline__ void mma_tf32(float* d, const uint32_t* a, const uint32_t* b) {
    asm volatile(
        "mma.sync.aligned.m16n8k8.row.col.f32.tf32.tf32.f32 "
        "{%0,%1,%2,%3}, {%4,%5,%6,%7}, {%8,%9}, {%0,%1,%2,%3};"
        : "+f"(d[0]), "+f"(d[1]), "+f"(d[2]), "+f"(d[3])
        : "r"(a[0]), "r"(a[1]), "r"(a[2]), "r"(a[3]), "r"(b[0]), "r"(b[1]));
}

template<bool RELU>
__global__ __launch_bounds__(256, 2)
void tgemm_bias(const float* __restrict__ A, const float* __restrict__ B,
                const float* __restrict__ bias, float* __restrict__ C,
                int M, int N, int K)
{
    __shared__ __align__(16) uint32_t As[128][36];
    __shared__ __align__(16) uint32_t Bs[128][36];

    const int tid  = threadIdx.x;
    const int lane = tid & 31;
    const int warp = tid >> 5;
    const int wm   = (warp & 3) * 32;   // warp m offset
    const int wn   = (warp >> 2) * 64;  // warp n offset
    const int bm   = blockIdx.y * 128;
    const int bn   = blockIdx.x * 128;

    const int qr = lane >> 2;  // 0..7
    const int qc = lane & 3;   // 0..3

    // global load mapping: 8 threads per row (float4 each), 32 rows per pass, 4 passes
    const int lr = tid >> 3;          // 0..31
    const int lc = (tid & 7) << 2;    // 0,4,...,28
    const float* Ag = A + (size_t)(bm + lr) * K + lc;
    const float* Bg = B + (size_t)(bn + lr) * K + lc;

    float acc[2][8][4];
#pragma unroll
    for (int i = 0; i < 2; i++)
#pragma unroll
        for (int j = 0; j < 8; j++)
#pragma unroll
            for (int t = 0; t < 4; t++) acc[i][j][t] = 0.f;

    for (int k0 = 0; k0 < K; k0 += 32) {
#pragma unroll
        for (int it = 0; it < 4; it++) {
            const int row = lr + it * 32;
            float4 av = *(const float4*)(Ag + (size_t)(it * 32) * K + k0);
            float4 bv = *(const float4*)(Bg + (size_t)(it * 32) * K + k0);
            uint4 at = make_uint4(f2tf(av.x), f2tf(av.y), f2tf(av.z), f2tf(av.w));
            uint4 bt = make_uint4(f2tf(bv.x), f2tf(bv.y), f2tf(bv.z), f2tf(bv.w));
            *(uint4*)&As[row][lc] = at;
            *(uint4*)&Bs[row][lc] = bt;
        }
        __syncthreads();

#pragma unroll
        for (int kk = 0; kk < 32; kk += 8) {
            uint32_t af[2][4];
#pragma unroll
            for (int i = 0; i < 2; i++) {
                const int r = wm + i * 16;
                af[i][0] = As[r + qr    ][kk + qc    ];
                af[i][1] = As[r + qr + 8][kk + qc    ];
                af[i][2] = As[r + qr    ][kk + qc + 4];
                af[i][3] = As[r + qr + 8][kk + qc + 4];
            }
            uint32_t bf[8][2];
#pragma unroll
            for (int j = 0; j < 8; j++) {
                const int c = wn + j * 8;
                bf[j][0] = Bs[c + qr][kk + qc    ];
                bf[j][1] = Bs[c + qr][kk + qc + 4];
            }
#pragma unroll
            for (int i = 0; i < 2; i++)
#pragma unroll
                for (int j = 0; j < 8; j++)
                    mma_tf32(acc[i][j], af[i], bf[j]);
        }
        __syncthreads();
    }

    // epilogue: bias (+ReLU), float2 stores
#pragma unroll
    for (int i = 0; i < 2; i++) {
        const int r0 = bm + wm + i * 16 + qr;
#pragma unroll
        for (int j = 0; j < 8; j++) {
            const int col = bn + wn + j * 8 + qc * 2;
            const float b0 = bias[col], b1 = bias[col + 1];
            float v0 = acc[i][j][0] + b0;
            float v1 = acc[i][j][1] + b1;
            float v2 = acc[i][j][2] + b0;
            float v3 = acc[i][j][3] + b1;
            if (RELU) {
                v0 = fmaxf(v0, 0.f); v1 = fmaxf(v1, 0.f);
                v2 = fmaxf(v2, 0.f); v3 = fmaxf(v3, 0.f);
            }
            *(float2*)&C[(size_t)r0 * N + col]       = make_float2(v0, v1);
            *(float2*)&C[(size_t)(r0 + 8) * N + col] = make_float2(v2, v3);
        }
    }
}

// ============================================================================
// Low-rank factor projection (float4-vectorized input loads):
//   k[b,a,h,r] = sum_kk Kp[b, a*16 + h/16, (h%16)*64 + kk] * fac[a, kk, r]
// ============================================================================
__global__ __launch_bounds__(256)
void factor_kernel(const float* __restrict__ Kp, const float* __restrict__ Vp,
                   const float* __restrict__ fac,
                   float* __restrict__ kf, float* __restrict__ vf)
{
    __shared__ float fs[KR][RANKD];
    const int a = blockIdx.x, b = blockIdx.y, h = threadIdx.x;

    for (int i = threadIdx.x; i < KR * RANKD; i += 256)
        ((float*)fs)[i] = fac[(size_t)a * KR * RANKD + i];
    __syncthreads();

    const size_t rowbase = ((size_t)b * KDIM + a * 16 + (h >> 4)) * DIM + (h & 15) * 64;
    const float4* kin = (const float4*)(Kp + rowbase);
    const float4* vin = (const float4*)(Vp + rowbase);

    float ak[RANKD], av[RANKD];
#pragma unroll
    for (int r = 0; r < RANKD; r++) { ak[r] = 0.f; av[r] = 0.f; }

#pragma unroll 4
    for (int q = 0; q < KR / 4; q++) {
        float4 k4 = kin[q];
        float4 v4 = vin[q];
        const float kv[4] = {k4.x, k4.y, k4.z, k4.w};
        const float vv[4] = {v4.x, v4.y, v4.z, v4.w};
#pragma unroll
        for (int s = 0; s < 4; s++) {
            const int kk = q * 4 + s;
#pragma unroll
            for (int r = 0; r < RANKD; r++) {
                ak[r] = fmaf(kv[s], fs[kk][r], ak[r]);
                av[r] = fmaf(vv[s], fs[kk][r], av[r]);
            }
        }
    }

    float4* ko = (float4*)(kf + (((size_t)b * AH + a) * HR + h) * RANKD);
    float4* vo = (float4*)(vf + (((size_t)b * AH + a) * HR + h) * RANKD);
#pragma unroll
    for (int r = 0; r < 4; r++) {
        ko[r] = make_float4(ak[4*r], ak[4*r+1], ak[4*r+2], ak[4*r+3]);
        vo[r] = make_float4(av[4*r], av[4*r+1], av[4*r+2], av[4*r+3]);
    }
}

// ============================================================================
// Fused attention per (b,a): scores + softmax(16) + ctx, written in (bs,seq,dim).
// ============================================================================
__global__ __launch_bounds__(128)
void attn_kernel(const float* __restrict__ Qp, const float* __restrict__ kf,
                 const float* __restrict__ vf, float* __restrict__ ctx)
{
    __shared__ float ks[HR][RANKD];
    __shared__ float vs[HR][RANKD];
    const int a = blockIdx.x, b = blockIdx.y;
    const int l = threadIdx.x;

    const size_t kvbase = ((size_t)b * AH + a) * HR * RANKD;
    for (int i = threadIdx.x; i < HR * RANKD; i += 128) {
        ((float*)ks)[i] = kf[kvbase + i];
        ((float*)vs)[i] = vf[kvbase + i];
    }
    __syncthreads();

    const float* Qb = Qp + ((size_t)b * SEQQ + a * 32) * DIM;

    float sc[RANKD];
#pragma unroll
    for (int r = 0; r < RANKD; r++) sc[r] = 0.f;

    for (int h = 0; h < HR; h++) {
        float qv = Qb[(h >> 3) * DIM + (h & 7) * LQ + l];
#pragma unroll
        for (int r = 0; r < RANKD; r++)
            sc[r] = fmaf(qv, ks[h][r], sc[r]);
    }

    float mx = -1e30f;
#pragma unroll
    for (int r = 0; r < RANKD; r++) { sc[r] *= 0.0625f; mx = fmaxf(mx, sc[r]); }
    float sum = 0.f;
#pragma unroll
    for (int r = 0; r < RANKD; r++) { sc[r] = expf(sc[r] - mx); sum += sc[r]; }
    float inv = 1.f / sum;
#pragma unroll
    for (int r = 0; r < RANKD; r++) sc[r] *= inv;

    float* crow = ctx + ((size_t)b * SEQQ + a * 32 + (l >> 2)) * DIM + (l & 3) * 256;
    for (int h0 = 0; h0 < HR; h0 += 4) {
        float o[4];
#pragma unroll
        for (int s = 0; s < 4; s++) {
            float v = 0.f;
#pragma unroll
            for (int r = 0; r < RANKD; r++)
                v = fmaf(sc[r], vs[h0 + s][r], v);
            o[s] = v;
        }
        *(float4*)&crow[h0] = make_float4(o[0], o[1], o[2], o[3]);
    }
}

// ============================================================================
// Residual + LayerNorm over dim=1024. One block (256 threads) per row.
// ============================================================================
__global__ __launch_bounds__(256)
void ln_residual(const float* __restrict__ Y, const float* __restrict__ Q,
                 const float* __restrict__ gamma, const float* __restrict__ beta,
                 float* __restrict__ out)
{
    const int row = blockIdx.x;
    const int tid = threadIdx.x;
    const float* y = Y + (size_t)row * DIM;
    const float* q = Q + (size_t)row * DIM;

    float x[4];
    float sum = 0.f, sq = 0.f;
#pragma unroll
    for (int i = 0; i < 4; i++) {
        int c = tid + i * 256;
        float v = y[c] + q[c];
        x[i] = v; sum += v; sq += v * v;
    }
#pragma unroll
    for (int o = 16; o; o >>= 1) {
        sum += __shfl_xor_sync(0xffffffffu, sum, o);
        sq  += __shfl_xor_sync(0xffffffffu, sq,  o);
    }
    __shared__ float rs[8], rq[8];
    __shared__ float smu, sinv;
    if ((tid & 31) == 0) { rs[tid >> 5] = sum; rq[tid >> 5] = sq; }
    __syncthreads();
    if (tid == 0) {
        float s = 0.f, s2 = 0.f;
        for (int i = 0; i < 8; i++) { s += rs[i]; s2 += rq[i]; }
        float mu  = s  * (1.0f / DIM);
        float var = s2 * (1.0f / DIM) - mu * mu;
        smu = mu;
        sinv = rsqrtf(var + 1e-5f);
    }
    __syncthreads();
    float mu = smu, inv = sinv;
    float* o = out + (size_t)row * DIM;
#pragma unroll
    for (int i = 0; i < 4; i++) {
        int c = tid + i * 256;
        o[c] = (x[i] - mu) * inv * gamma[c] + beta[c];
    }
}

// ============================================================================
// kernel_launch: 8 graph-capturable launches on the default stream.
// ============================================================================
extern "C" void kernel_launch(void* const* d_in, const int* in_sizes, int n_in,
                              void* d_out, int out_size)
{
    const float* Q   = (const float*)d_in[0];
    const float* K   = (const float*)d_in[1];
    const float* V   = (const float*)d_in[2];
    const float* WQ  = (const float*)d_in[3];
    const float* bQ  = (const float*)d_in[4];
    const float* WK  = (const float*)d_in[5];
    const float* bK  = (const float*)d_in[6];
    const float* WV  = (const float*)d_in[7];
    const float* bV  = (const float*)d_in[8];
    const float* fac = (const float*)d_in[9];
    const float* W1  = (const float*)d_in[10];
    const float* b1  = (const float*)d_in[11];
    const float* W2  = (const float*)d_in[12];
    const float* b2  = (const float*)d_in[13];
    const float* gam = (const float*)d_in[14];
    const float* bet = (const float*)d_in[15];
    float* out = (float*)d_out;

    float *Qp, *Kp, *Vp, *kf, *vf, *ctx, *h1, *y;
    cudaGetSymbolAddress((void**)&Qp,  g_Qp);
    cudaGetSymbolAddress((void**)&Kp,  g_Kp);
    cudaGetSymbolAddress((void**)&Vp,  g_Vp);
    cudaGetSymbolAddress((void**)&kf,  g_kf);
    cudaGetSymbolAddress((void**)&vf,  g_vf);
    cudaGetSymbolAddress((void**)&ctx, g_ctx);
    cudaGetSymbolAddress((void**)&h1,  g_h1);
    cudaGetSymbolAddress((void**)&y,   g_y);

    const int MQ = BS_ * SEQQ;   // 32768
    const int MK = BS_ * KDIM;   // 16384

    // Projections (TF32 tensor cores)
    tgemm_bias<false><<<dim3(DIM / 128, MQ / 128), 256>>>(Q, WQ, bQ, Qp, MQ, DIM, DIM);
    tgemm_bias<false><<<dim3(DIM / 128, MK / 128), 256>>>(K, WK, bK, Kp, MK, DIM, DIM);
    tgemm_bias<false><<<dim3(DIM / 128, MK / 128), 256>>>(V, WV, bV, Vp, MK, DIM, DIM);

    // Low-rank factor projection of K/V
    factor_kernel<<<dim3(AH, BS_), 256>>>(Kp, Vp, fac, kf, vf);

    // Fused attention
    attn_kernel<<<dim3(AH, BS_), 128>>>(Qp, kf, vf, ctx);

    // FFN (TF32 tensor cores)
    tgemm_bias<true ><<<dim3(HID / 128, MQ / 128), 256>>>(ctx, W1, b1, h1, MQ, HID, DIM);
    tgemm_bias<false><<<dim3(DIM / 128, MQ / 128), 256>>>(h1,  W2, b2, y,  MQ, DIM, HID);

    // Residual + LayerNorm
    ln_residual<<<MQ, 256>>>(y, Q, gam, bet, out);
}

// round 14
// speedup vs baseline: 1.0016x; 1.0016x over previous
#include <cuda_runtime.h>
#include <cstdint>

#define BS_  16
#define SEQQ 2048
#define DIM  1024
#define KDIM 1024
#define AH   64
#define HR   256
#define RANKD 16
#define KR   64
#define LQ   128
#define HID  2048

// ---- scratch (no allocations allowed; __device__ globals are the sanctioned path) ----
__device__ float g_Qp [BS_*SEQQ*DIM];
__device__ float g_Kp [BS_*KDIM*DIM];
__device__ float g_Vp [BS_*KDIM*DIM];
__device__ float g_kf [BS_*AH*HR*RANKD];
__device__ float g_vf [BS_*AH*HR*RANKD];
__device__ float g_ctx[BS_*SEQQ*DIM];
__device__ float g_h1 [BS_*SEQQ*HID];
__device__ float g_y  [BS_*SEQQ*DIM];

// ============================================================================
// TF32 tensor-core GEMM: C[m,n] = sum_k A[m,k]*B[n,k] + bias[n]
// A row-major [M,K], B row-major [N,K]. M%128==0, N%128==0, K%32==0.
// 128x128x32 CTA tile, 8 warps (4m x 2n), warp tile 32x64, m16n8k8 tf32 MMA.
// Smem stride 36 words -> conflict-free fragment reads.
// ============================================================================
__device__ __forceinline__ uint32_t f2tf(float x) {
    uint32_t r;
    asm("cvt.rna.tf32.f32 %0, %1;" : "=r"(r) : "f"(x));
    return r;
}

__device__ __forceinline__ void mma_tf32(float* d, const uint32_t* a, const uint32_t* b) {
    asm volatile(
        "mma.sync.aligned.m16n8k8.row.col.f32.tf32.tf32.f32 "
        "{%0,%1,%2,%3}, {%4,%5,%6,%7}, {%8,%9}, {%0,%1,%2,%3};"
        : "+f"(d[0]), "+f"(d[1]), "+f"(d[2]), "+f"(d[3])
        : "r"(a[0]), "r"(a[1]), "r"(a[2]), "r"(a[3]), "r"(b[0]), "r"(b[1]));
}

template<bool RELU>
__global__ __launch_bounds__(256, 2)
void tgemm_bias(const float* __restrict__ A, const float* __restrict__ B,
                const float* __restrict__ bias, float* __restrict__ C,
                int M, int N, int K)
{
    __shared__ __align__(16) uint32_t As[128][36];
    __shared__ __align__(16) uint32_t Bs[128][36];

    const int tid  = threadIdx.x;
    const int lane = tid & 31;
    const int warp = tid >> 5;
    const int wm   = (warp & 3) * 32;   // warp m offset
    const int wn   = (warp >> 2) * 64;  // warp n offset
    const int bm   = blockIdx.y * 128;
    const int bn   = blockIdx.x * 128;

    const int qr = lane >> 2;  // 0..7
    const int qc = lane & 3;   // 0..3

    // global load mapping: 8 threads per row (float4 each), 32 rows per pass, 4 passes
    const int lr = tid >> 3;          // 0..31
    const int lc = (tid & 7) << 2;    // 0,4,...,28
    const float* Ag = A + (size_t)(bm + lr) * K + lc;
    const float* Bg = B + (size_t)(bn + lr) * K + lc;

    float acc[2][8][4];
#pragma unroll
    for (int i = 0; i < 2; i++)
#pragma unroll
        for (int j = 0; j < 8; j++)
#pragma unroll
            for (int t = 0; t < 4; t++) acc[i][j][t] = 0.f;

    for (int k0 = 0; k0 < K; k0 += 32) {
#pragma unroll
        for (int it = 0; it < 4; it++) {
            const int row = lr + it * 32;
            float4 av = *(const float4*)(Ag + (size_t)(it * 32) * K + k0);
            float4 bv = *(const float4*)(Bg + (size_t)(it * 32) * K + k0);
            uint4 at = make_uint4(f2tf(av.x), f2tf(av.y), f2tf(av.z), f2tf(av.w));
            uint4 bt = make_uint4(f2tf(bv.x), f2tf(bv.y), f2tf(bv.z), f2tf(bv.w));
            *(uint4*)&As[row][lc] = at;
            *(uint4*)&Bs[row][lc] = bt;
        }
        __syncthreads();

#pragma unroll
        for (int kk = 0; kk < 32; kk += 8) {
            uint32_t af[2][4];
#pragma unroll
            for (int i = 0; i < 2; i++) {
                const int r = wm + i * 16;
                af[i][0] = As[r + qr    ][kk + qc    ];
                af[i][1] = As[r + qr + 8][kk + qc    ];
                af[i][2] = As[r + qr    ][kk + qc + 4];
                af[i][3] = As[r + qr + 8][kk + qc + 4];
            }
            uint32_t bf[8][2];
#pragma unroll
            for (int j = 0; j < 8; j++) {
                const int c = wn + j * 8;
                bf[j][0] = Bs[c + qr][kk + qc    ];
                bf[j][1] = Bs[c + qr][kk + qc + 4];
            }
#pragma unroll
            for (int i = 0; i < 2; i++)
#pragma unroll
                for (int j = 0; j < 8; j++)
                    mma_tf32(acc[i][j], af[i], bf[j]);
        }
        __syncthreads();
    }

    // epilogue: bias (+ReLU), float2 stores
#pragma unroll
    for (int i = 0; i < 2; i++) {
        const int r0 = bm + wm + i * 16 + qr;
#pragma unroll
        for (int j = 0; j < 8; j++) {
            const int col = bn + wn + j * 8 + qc * 2;
            const float b0 = bias[col], b1 = bias[col + 1];
            float v0 = acc[i][j][0] + b0;
            float v1 = acc[i][j][1] + b1;
            float v2 = acc[i][j][2] + b0;
            float v3 = acc[i][j][3] + b1;
            if (RELU) {
                v0 = fmaxf(v0, 0.f); v1 = fmaxf(v1, 0.f);
                v2 = fmaxf(v2, 0.f); v3 = fmaxf(v3, 0.f);
            }
            *(float2*)&C[(size_t)r0 * N + col]       = make_float2(v0, v1);
            *(float2*)&C[(size_t)(r0 + 8) * N + col] = make_float2(v2, v3);
        }
    }
}

// ============================================================================
// Low-rank factor projection (float4-vectorized input loads):
//   k[b,a,h,r] = sum_kk Kp[b, a*16 + h/16, (h%16)*64 + kk] * fac[a, kk, r]
// ============================================================================
__global__ __launch_bounds__(256)
void factor_kernel(const float* __restrict__ Kp, const float* __restrict__ Vp,
                   const float* __restrict__ fac,
                   float* __restrict__ kf, float* __restrict__ vf)
{
    __shared__ float fs[KR][RANKD];
    const int a = blockIdx.x, b = blockIdx.y, h = threadIdx.x;

    for (int i = threadIdx.x; i < KR * RANKD; i += 256)
        ((float*)fs)[i] = fac[(size_t)a * KR * RANKD + i];
    __syncthreads();

    const size_t rowbase = ((size_t)b * KDIM + a * 16 + (h >> 4)) * DIM + (h & 15) * 64;
    const float4* kin = (const float4*)(Kp + rowbase);
    const float4* vin = (const float4*)(Vp + rowbase);

    float ak[RANKD], av[RANKD];
#pragma unroll
    for (int r = 0; r < RANKD; r++) { ak[r] = 0.f; av[r] = 0.f; }

#pragma unroll 4
    for (int q = 0; q < KR / 4; q++) {
        float4 k4 = kin[q];
        float4 v4 = vin[q];
        const float kv[4] = {k4.x, k4.y, k4.z, k4.w};
        const float vv[4] = {v4.x, v4.y, v4.z, v4.w};
#pragma unroll
        for (int s = 0; s < 4; s++) {
            const int kk = q * 4 + s;
#pragma unroll
            for (int r = 0; r < RANKD; r++) {
                ak[r] = fmaf(kv[s], fs[kk][r], ak[r]);
                av[r] = fmaf(vv[s], fs[kk][r], av[r]);
            }
        }
    }

    float4* ko = (float4*)(kf + (((size_t)b * AH + a) * HR + h) * RANKD);
    float4* vo = (float4*)(vf + (((size_t)b * AH + a) * HR + h) * RANKD);
#pragma unroll
    for (int r = 0; r < 4; r++) {
        ko[r] = make_float4(ak[4*r], ak[4*r+1], ak[4*r+2], ak[4*r+3]);
        vo[r] = make_float4(av[4*r], av[4*r+1], av[4*r+2], av[4*r+3]);
    }
}

// ============================================================================
// Fused attention per (b,a): scores + softmax(16) + ctx, written in (bs,seq,dim).
// ============================================================================
__global__ __launch_bounds__(128)
void attn_kernel(const float* __restrict__ Qp, const float* __restrict__ kf,
                 const float* __restrict__ vf, float* __restrict__ ctx)
{
    __shared__ float ks[HR][RANKD];
    __shared__ float vs[HR][RANKD];
    const int a = blockIdx.x, b = blockIdx.y;
    const int l = threadIdx.x;

    const size_t kvbase = ((size_t)b * AH + a) * HR * RANKD;
    for (int i = threadIdx.x; i < HR * RANKD; i += 128) {
        ((float*)ks)[i] = kf[kvbase + i];
        ((float*)vs)[i] = vf[kvbase + i];
    }
    __syncthreads();

    const float* Qb = Qp + ((size_t)b * SEQQ + a * 32) * DIM;

    float sc[RANKD];
#pragma unroll
    for (int r = 0; r < RANKD; r++) sc[r] = 0.f;

    for (int h = 0; h < HR; h++) {
        float qv = Qb[(h >> 3) * DIM + (h & 7) * LQ + l];
#pragma unroll
        for (int r = 0; r < RANKD; r++)
            sc[r] = fmaf(qv, ks[h][r], sc[r]);
    }

    float mx = -1e30f;
#pragma unroll
    for (int r = 0; r < RANKD; r++) { sc[r] *= 0.0625f; mx = fmaxf(mx, sc[r]); }
    float sum = 0.f;
#pragma unroll
    for (int r = 0; r < RANKD; r++) { sc[r] = expf(sc[r] - mx); sum += sc[r]; }
    float inv = 1.f / sum;
#pragma unroll
    for (int r = 0; r < RANKD; r++) sc[r] *= inv;

    float* crow = ctx + ((size_t)b * SEQQ + a * 32 + (l >> 2)) * DIM + (l & 3) * 256;
    for (int h0 = 0; h0 < HR; h0 += 4) {
        float o[4];
#pragma unroll
        for (int s = 0; s < 4; s++) {
            float v = 0.f;
#pragma unroll
            for (int r = 0; r < RANKD; r++)
                v = fmaf(sc[r], vs[h0 + s][r], v);
            o[s] = v;
        }
        *(float4*)&crow[h0] = make_float4(o[0], o[1], o[2], o[3]);
    }
}

// ============================================================================
// Residual + LayerNorm over dim=1024. One block (256 threads) per row.
// ============================================================================
__global__ __launch_bounds__(256)
void ln_residual(const float* __restrict__ Y, const float* __restrict__ Q,
                 const float* __restrict__ gamma, const float* __restrict__ beta,
                 float* __restrict__ out)
{
    const int row = blockIdx.x;
    const int tid = threadIdx.x;
    const float* y = Y + (size_t)row * DIM;
    const float* q = Q + (size_t)row * DIM;

    float x[4];
    float sum = 0.f, sq = 0.f;
#pragma unroll
    for (int i = 0; i < 4; i++) {
        int c = tid + i * 256;
        float v = y[c] + q[c];
        x[i] = v; sum += v; sq += v * v;
    }
#pragma unroll
    for (int o = 16; o; o >>= 1) {
        sum += __shfl_xor_sync(0xffffffffu, sum, o);
        sq  += __shfl_xor_sync(0xffffffffu, sq,  o);
    }
    __shared__ float rs[8], rq[8];
    __shared__ float smu, sinv;
    if ((tid & 31) == 0) { rs[tid >> 5] = sum; rq[tid >> 5] = sq; }
    __syncthreads();
    if (tid == 0) {
        float s = 0.f, s2 = 0.f;
        for (int i = 0; i < 8; i++) { s += rs[i]; s2 += rq[i]; }
        float mu  = s  * (1.0f / DIM);
        float var = s2 * (1.0f / DIM) - mu * mu;
        smu = mu;
        sinv = rsqrtf(var + 1e-5f);
    }
    __syncthreads();
    float mu = smu, inv = sinv;
    float* o = out + (size_t)row * DIM;
#pragma unroll
    for (int i = 0; i < 4; i++) {
        int c = tid + i * 256;
        o[c] = (x[i] - mu) * inv * gamma[c] + beta[c];
    }
}

// ============================================================================
// kernel_launch: 8 graph-capturable launches on the default stream.
// ============================================================================
extern "C" void kernel_launch(void* const* d_in, const int* in_sizes, int n_in,
                              void* d_out, int out_size)
{
    const float* Q   = (const float*)d_in[0];
    const float* K   = (const float*)d_in[1];
    const float* V   = (const float*)d_in[2];
    const float* WQ  = (const float*)d_in[3];
    const float* bQ  = (const float*)d_in[4];
    const float* WK  = (const float*)d_in[5];
    const float* bK  = (const float*)d_in[6];
    const float* WV  = (const float*)d_in[7];
    const float* bV  = (const float*)d_in[8];
    const float* fac = (const float*)d_in[9];
    const float* W1  = (const float*)d_in[10];
    const float* b1  = (const float*)d_in[11];
    const float* W2  = (const float*)d_in[12];
    const float* b2  = (const float*)d_in[13];
    const float* gam = (const float*)d_in[14];
    const float* bet = (const float*)d_in[15];
    float* out = (float*)d_out;

    float *Qp, *Kp, *Vp, *kf, *vf, *ctx, *h1, *y;
    cudaGetSymbolAddress((void**)&Qp,  g_Qp);
    cudaGetSymbolAddress((void**)&Kp,  g_Kp);
    cudaGetSymbolAddress((void**)&Vp,  g_Vp);
    cudaGetSymbolAddress((void**)&kf,  g_kf);
    cudaGetSymbolAddress((void**)&vf,  g_vf);
    cudaGetSymbolAddress((void**)&ctx, g_ctx);
    cudaGetSymbolAddress((void**)&h1,  g_h1);
    cudaGetSymbolAddress((void**)&y,   g_y);

    const int MQ = BS_ * SEQQ;   // 32768
    const int MK = BS_ * KDIM;   // 16384

    // Projections (TF32 tensor cores)
    tgemm_bias<false><<<dim3(DIM / 128, MQ / 128), 256>>>(Q, WQ, bQ, Qp, MQ, DIM, DIM);
    tgemm_bias<false><<<dim3(DIM / 128, MK / 128), 256>>>(K, WK, bK, Kp, MK, DIM, DIM);
    tgemm_bias<false><<<dim3(DIM / 128, MK / 128), 256>>>(V, WV, bV, Vp, MK, DIM, DIM);

    // Low-rank factor projection of K/V
    factor_kernel<<<dim3(AH, BS_), 256>>>(Kp, Vp, fac, kf, vf);

    // Fused attention
    attn_kernel<<<dim3(AH, BS_), 128>>>(Qp, kf, vf, ctx);

    // FFN (TF32 tensor cores)
    tgemm_bias<true ><<<dim3(HID / 128, MQ / 128), 256>>>(ctx, W1, b1, h1, MQ, HID, DIM);
    tgemm_bias<false><<<dim3(DIM / 128, MQ / 128), 256>>>(h1,  W2, b2, y,  MQ, DIM, HID);

    // Residual + LayerNorm
    ln_residual<<<MQ, 256>>>(y, Q, gam, bet, out);
}

// round 15
// speedup vs baseline: 1.0466x; 1.0449x over previous
#include <cuda_runtime.h>
#include <cstdint>

#define BS_  16
#define SEQQ 2048
#define DIM  1024
#define KDIM 1024
#define AH   64
#define HR   256
#define RANKD 16
#define KR   64
#define LQ   128
#define HID  2048

// ---- scratch (no allocations allowed; __device__ globals are the sanctioned path) ----
__device__ float g_Qp [BS_*SEQQ*DIM];
__device__ float g_Kp [BS_*KDIM*DIM];
__device__ float g_Vp [BS_*KDIM*DIM];
__device__ float g_kf [BS_*AH*HR*RANKD];
__device__ float g_vf [BS_*AH*HR*RANKD];
__device__ float g_ctx[BS_*SEQQ*DIM];
__device__ float g_h1 [BS_*SEQQ*HID];
__device__ float g_y  [BS_*SEQQ*DIM];

// ============================================================================
// TF32 tensor-core GEMM with double-buffered cp.async pipeline.
//   C[m,n] = sum_k A[m,k]*B[n,k] + bias[n]
// A row-major [M,K], B row-major [N,K]. M%128==0, N%128==0, K%32==0.
// 128x128x32 CTA tile, 8 warps (4m x 2n), warp tile 32x64, m16n8k8 tf32 MMA.
// Smem: fp32 staged via LDGSTS; tf32 rounding (cvt.rna) at fragment read.
// Stride 36 words -> conflict-free fragment reads (bank = 4*qr+qc, bijective).
// ============================================================================
__device__ __forceinline__ uint32_t f2tf(float x) {
    uint32_t r;
    asm("cvt.rna.tf32.f32 %0, %1;" : "=r"(r) : "f"(x));
    return r;
}

__device__ __forceinline__ void mma_tf32(float* d, const uint32_t* a, const uint32_t* b) {
    asm volatile(
        "mma.sync.aligned.m16n8k8.row.col.f32.tf32.tf32.f32 "
        "{%0,%1,%2,%3}, {%4,%5,%6,%7}, {%8,%9}, {%0,%1,%2,%3};"
        : "+f"(d[0]), "+f"(d[1]), "+f"(d[2]), "+f"(d[3])
        : "r"(a[0]), "r"(a[1]), "r"(a[2]), "r"(a[3]), "r"(b[0]), "r"(b[1]));
}

__device__ __forceinline__ uint32_t smem_u32(const void* p) {
    uint32_t r;
    asm("{ .reg .u64 t; cvta.to.shared.u64 t, %1; cvt.u32.u64 %0, t; }"
        : "=r"(r) : "l"(p));
    return r;
}

__device__ __forceinline__ void cp16(uint32_t dst, const float* src) {
    asm volatile("cp.async.cg.shared.global [%0], [%1], 16;" :: "r"(dst), "l"(src));
}

#define LDW   36                      // smem row stride in words
#define STAGE (128 * LDW)             // words per (A or B) stage
#define GEMM_SMEM_BYTES (4 * STAGE * 4 /*bytes*/)   // 2 stages x (A+B) = 73728 B

template<bool RELU>
__global__ __launch_bounds__(256, 2)
void tgemm_bias(const float* __restrict__ A, const float* __restrict__ B,
                const float* __restrict__ bias, float* __restrict__ C,
                int M, int N, int K)
{
    extern __shared__ float sm[];
    // layout: [ As stage0 | As stage1 | Bs stage0 | Bs stage1 ]
    const uint32_t sm_u  = smem_u32(sm);

    const int tid  = threadIdx.x;
    const int lane = tid & 31;
    const int warp = tid >> 5;
    const int wm   = (warp & 3) * 32;
    const int wn   = (warp >> 2) * 64;
    const int bm   = blockIdx.y * 128;
    const int bn   = blockIdx.x * 128;

    const int qr = lane >> 2;
    const int qc = lane & 3;

    // global load mapping: 8 threads per row (16B each), 32 rows/pass, 4 passes
    const int lr = tid >> 3;          // 0..31
    const int lc = (tid & 7) << 2;    // 0,4,...,28
    const float* Ag = A + (size_t)(bm + lr) * K + lc;
    const float* Bg = B + (size_t)(bn + lr) * K + lc;

    // per-thread smem store addresses (bytes), stage 0
    const uint32_t dA0 = sm_u + (uint32_t)((lr * LDW + lc) * 4);
    const uint32_t dB0 = dA0 + 2 * STAGE * 4;

    float acc[2][8][4];
#pragma unroll
    for (int i = 0; i < 2; i++)
#pragma unroll
        for (int j = 0; j < 8; j++)
#pragma unroll
            for (int t = 0; t < 4; t++) acc[i][j][t] = 0.f;

    const int nt = K >> 5;

    // ---- prologue: prefetch stage 0 ----
#pragma unroll
    for (int it = 0; it < 4; it++) {
        cp16(dA0 + (uint32_t)(it * 32 * LDW * 4), Ag + (size_t)(it * 32) * K);
        cp16(dB0 + (uint32_t)(it * 32 * LDW * 4), Bg + (size_t)(it * 32) * K);
    }
    asm volatile("cp.async.commit_group;");

    for (int t = 0; t < nt; t++) {
        const int s = t & 1;
        if (t + 1 < nt) {
            const int k0 = (t + 1) << 5;
            const uint32_t off = (uint32_t)((s ^ 1) * STAGE * 4);
#pragma unroll
            for (int it = 0; it < 4; it++) {
                cp16(dA0 + off + (uint32_t)(it * 32 * LDW * 4), Ag + (size_t)(it * 32) * K + k0);
                cp16(dB0 + off + (uint32_t)(it * 32 * LDW * 4), Bg + (size_t)(it * 32) * K + k0);
            }
            asm volatile("cp.async.commit_group;");
            asm volatile("cp.async.wait_group 1;");
        } else {
            asm volatile("cp.async.wait_group 0;");
        }
        __syncthreads();

        const float* Asb = sm + s * STAGE;
        const float* Bsb = sm + (2 + s) * STAGE;

#pragma unroll
        for (int kk = 0; kk < 32; kk += 8) {
            uint32_t af[2][4];
#pragma unroll
            for (int i = 0; i < 2; i++) {
                const int r = wm + i * 16;
                af[i][0] = f2tf(Asb[(r + qr    ) * LDW + kk + qc    ]);
                af[i][1] = f2tf(Asb[(r + qr + 8) * LDW + kk + qc    ]);
                af[i][2] = f2tf(Asb[(r + qr    ) * LDW + kk + qc + 4]);
                af[i][3] = f2tf(Asb[(r + qr + 8) * LDW + kk + qc + 4]);
            }
            uint32_t bf[8][2];
#pragma unroll
            for (int j = 0; j < 8; j++) {
                const int c = wn + j * 8;
                bf[j][0] = f2tf(Bsb[(c + qr) * LDW + kk + qc    ]);
                bf[j][1] = f2tf(Bsb[(c + qr) * LDW + kk + qc + 4]);
            }
#pragma unroll
            for (int i = 0; i < 2; i++)
#pragma unroll
                for (int j = 0; j < 8; j++)
                    mma_tf32(acc[i][j], af[i], bf[j]);
        }
        __syncthreads();   // stage s free before iter t+1 prefetches into it
    }

    // epilogue: bias (+ReLU), float2 stores
#pragma unroll
    for (int i = 0; i < 2; i++) {
        const int r0 = bm + wm + i * 16 + qr;
#pragma unroll
        for (int j = 0; j < 8; j++) {
            const int col = bn + wn + j * 8 + qc * 2;
            const float b0 = bias[col], b1 = bias[col + 1];
            float v0 = acc[i][j][0] + b0;
            float v1 = acc[i][j][1] + b1;
            float v2 = acc[i][j][2] + b0;
            float v3 = acc[i][j][3] + b1;
            if (RELU) {
                v0 = fmaxf(v0, 0.f); v1 = fmaxf(v1, 0.f);
                v2 = fmaxf(v2, 0.f); v3 = fmaxf(v3, 0.f);
            }
            *(float2*)&C[(size_t)r0 * N + col]       = make_float2(v0, v1);
            *(float2*)&C[(size_t)(r0 + 8) * N + col] = make_float2(v2, v3);
        }
    }
}

// ============================================================================
// Low-rank factor projection (float4-vectorized input loads)
// ============================================================================
__global__ __launch_bounds__(256)
void factor_kernel(const float* __restrict__ Kp, const float* __restrict__ Vp,
                   const float* __restrict__ fac,
                   float* __restrict__ kf, float* __restrict__ vf)
{
    __shared__ float fs[KR][RANKD];
    const int a = blockIdx.x, b = blockIdx.y, h = threadIdx.x;

    for (int i = threadIdx.x; i < KR * RANKD; i += 256)
        ((float*)fs)[i] = fac[(size_t)a * KR * RANKD + i];
    __syncthreads();

    const size_t rowbase = ((size_t)b * KDIM + a * 16 + (h >> 4)) * DIM + (h & 15) * 64;
    const float4* kin = (const float4*)(Kp + rowbase);
    const float4* vin = (const float4*)(Vp + rowbase);

    float ak[RANKD], av[RANKD];
#pragma unroll
    for (int r = 0; r < RANKD; r++) { ak[r] = 0.f; av[r] = 0.f; }

#pragma unroll 4
    for (int q = 0; q < KR / 4; q++) {
        float4 k4 = kin[q];
        float4 v4 = vin[q];
        const float kv[4] = {k4.x, k4.y, k4.z, k4.w};
        const float vv[4] = {v4.x, v4.y, v4.z, v4.w};
#pragma unroll
        for (int s = 0; s < 4; s++) {
            const int kk = q * 4 + s;
#pragma unroll
            for (int r = 0; r < RANKD; r++) {
                ak[r] = fmaf(kv[s], fs[kk][r], ak[r]);
                av[r] = fmaf(vv[s], fs[kk][r], av[r]);
            }
        }
    }

    float4* ko = (float4*)(kf + (((size_t)b * AH + a) * HR + h) * RANKD);
    float4* vo = (float4*)(vf + (((size_t)b * AH + a) * HR + h) * RANKD);
#pragma unroll
    for (int r = 0; r < 4; r++) {
        ko[r] = make_float4(ak[4*r], ak[4*r+1], ak[4*r+2], ak[4*r+3]);
        vo[r] = make_float4(av[4*r], av[4*r+1], av[4*r+2], av[4*r+3]);
    }
}

// ============================================================================
// Fused attention per (b,a): scores + softmax(16) + ctx, written in (bs,seq,dim).
// ============================================================================
__global__ __launch_bounds__(128)
void attn_kernel(const float* __restrict__ Qp, const float* __restrict__ kf,
                 const float* __restrict__ vf, float* __restrict__ ctx)
{
    __shared__ float ks[HR][RANKD];
    __shared__ float vs[HR][RANKD];
    const int a = blockIdx.x, b = blockIdx.y;
    const int l = threadIdx.x;

    const size_t kvbase = ((size_t)b * AH + a) * HR * RANKD;
    for (int i = threadIdx.x; i < HR * RANKD; i += 128) {
        ((float*)ks)[i] = kf[kvbase + i];
        ((float*)vs)[i] = vf[kvbase + i];
    }
    __syncthreads();

    const float* Qb = Qp + ((size_t)b * SEQQ + a * 32) * DIM;

    float sc[RANKD];
#pragma unroll
    for (int r = 0; r < RANKD; r++) sc[r] = 0.f;

    for (int h = 0; h < HR; h++) {
        float qv = Qb[(h >> 3) * DIM + (h & 7) * LQ + l];
#pragma unroll
        for (int r = 0; r < RANKD; r++)
            sc[r] = fmaf(qv, ks[h][r], sc[r]);
    }

    float mx = -1e30f;
#pragma unroll
    for (int r = 0; r < RANKD; r++) { sc[r] *= 0.0625f; mx = fmaxf(mx, sc[r]); }
    float sum = 0.f;
#pragma unroll
    for (int r = 0; r < RANKD; r++) { sc[r] = expf(sc[r] - mx); sum += sc[r]; }
    float inv = 1.f / sum;
#pragma unroll
    for (int r = 0; r < RANKD; r++) sc[r] *= inv;

    float* crow = ctx + ((size_t)b * SEQQ + a * 32 + (l >> 2)) * DIM + (l & 3) * 256;
    for (int h0 = 0; h0 < HR; h0 += 4) {
        float o[4];
#pragma unroll
        for (int s = 0; s < 4; s++) {
            float v = 0.f;
#pragma unroll
            for (int r = 0; r < RANKD; r++)
                v = fmaf(sc[r], vs[h0 + s][r], v);
            o[s] = v;
        }
        *(float4*)&crow[h0] = make_float4(o[0], o[1], o[2], o[3]);
    }
}

// ============================================================================
// Residual + LayerNorm over dim=1024. One block (256 threads) per row.
// ============================================================================
__global__ __launch_bounds__(256)
void ln_residual(const float* __restrict__ Y, const float* __restrict__ Q,
                 const float* __restrict__ gamma, const float* __restrict__ beta,
                 float* __restrict__ out)
{
    const int row = blockIdx.x;
    const int tid = threadIdx.x;
    const float* y = Y + (size_t)row * DIM;
    const float* q = Q + (size_t)row * DIM;

    float x[4];
    float sum = 0.f, sq = 0.f;
#pragma unroll
    for (int i = 0; i < 4; i++) {
        int c = tid + i * 256;
        float v = y[c] + q[c];
        x[i] = v; sum += v; sq += v * v;
    }
#pragma unroll
    for (int o = 16; o; o >>= 1) {
        sum += __shfl_xor_sync(0xffffffffu, sum, o);
        sq  += __shfl_xor_sync(0xffffffffu, sq,  o);
    }
    __shared__ float rs[8], rq[8];
    __shared__ float smu, sinv;
    if ((tid & 31) == 0) { rs[tid >> 5] = sum; rq[tid >> 5] = sq; }
    __syncthreads();
    if (tid == 0) {
        float s = 0.f, s2 = 0.f;
        for (int i = 0; i < 8; i++) { s += rs[i]; s2 += rq[i]; }
        float mu  = s  * (1.0f / DIM);
        float var = s2 * (1.0f / DIM) - mu * mu;
        smu = mu;
        sinv = rsqrtf(var + 1e-5f);
    }
    __syncthreads();
    float mu = smu, inv = sinv;
    float* o = out + (size_t)row * DIM;
#pragma unroll
    for (int i = 0; i < 4; i++) {
        int c = tid + i * 256;
        o[c] = (x[i] - mu) * inv * gamma[c] + beta[c];
    }
}

// ============================================================================
// kernel_launch: 8 graph-capturable launches on the default stream.
// ============================================================================
extern "C" void kernel_launch(void* const* d_in, const int* in_sizes, int n_in,
                              void* d_out, int out_size)
{
    const float* Q   = (const float*)d_in[0];
    const float* K   = (const float*)d_in[1];
    const float* V   = (const float*)d_in[2];
    const float* WQ  = (const float*)d_in[3];
    const float* bQ  = (const float*)d_in[4];
    const float* WK  = (const float*)d_in[5];
    const float* bK  = (const float*)d_in[6];
    const float* WV  = (const float*)d_in[7];
    const float* bV  = (const float*)d_in[8];
    const float* fac = (const float*)d_in[9];
    const float* W1  = (const float*)d_in[10];
    const float* b1  = (const float*)d_in[11];
    const float* W2  = (const float*)d_in[12];
    const float* b2  = (const float*)d_in[13];
    const float* gam = (const float*)d_in[14];
    const float* bet = (const float*)d_in[15];
    float* out = (float*)d_out;

    float *Qp, *Kp, *Vp, *kf, *vf, *ctx, *h1, *y;
    cudaGetSymbolAddress((void**)&Qp,  g_Qp);
    cudaGetSymbolAddress((void**)&Kp,  g_Kp);
    cudaGetSymbolAddress((void**)&Vp,  g_Vp);
    cudaGetSymbolAddress((void**)&kf,  g_kf);
    cudaGetSymbolAddress((void**)&vf,  g_vf);
    cudaGetSymbolAddress((void**)&ctx, g_ctx);
    cudaGetSymbolAddress((void**)&h1,  g_h1);
    cudaGetSymbolAddress((void**)&y,   g_y);

    static bool attr_done = false;
    if (!attr_done) {
        cudaFuncSetAttribute(tgemm_bias<false>,
                             cudaFuncAttributeMaxDynamicSharedMemorySize, GEMM_SMEM_BYTES);
        cudaFuncSetAttribute(tgemm_bias<true>,
                             cudaFuncAttributeMaxDynamicSharedMemorySize, GEMM_SMEM_BYTES);
        attr_done = true;
    }

    const int MQ = BS_ * SEQQ;   // 32768
    const int MK = BS_ * KDIM;   // 16384

    // Projections (TF32 tensor cores, cp.async double-buffered)
    tgemm_bias<false><<<dim3(DIM / 128, MQ / 128), 256, GEMM_SMEM_BYTES>>>(Q, WQ, bQ, Qp, MQ, DIM, DIM);
    tgemm_bias<false><<<dim3(DIM / 128, MK / 128), 256, GEMM_SMEM_BYTES>>>(K, WK, bK, Kp, MK, DIM, DIM);
    tgemm_bias<false><<<dim3(DIM / 128, MK / 128), 256, GEMM_SMEM_BYTES>>>(V, WV, bV, Vp, MK, DIM, DIM);

    // Low-rank factor projection of K/V
    factor_kernel<<<dim3(AH, BS_), 256>>>(Kp, Vp, fac, kf, vf);

    // Fused attention
    attn_kernel<<<dim3(AH, BS_), 128>>>(Qp, kf, vf, ctx);

    // FFN (TF32 tensor cores, cp.async double-buffered)
    tgemm_bias<true ><<<dim3(HID / 128, MQ / 128), 256, GEMM_SMEM_BYTES>>>(ctx, W1, b1, h1, MQ, HID, DIM);
    tgemm_bias<false><<<dim3(DIM / 128, MQ / 128), 256, GEMM_SMEM_BYTES>>>(h1,  W2, b2, y,  MQ, DIM, HID);

    // Residual + LayerNorm
    ln_residual<<<MQ, 256>>>(y, Q, gam, bet, out);
}